// round 10
// baseline (speedup 1.0000x reference)
#include <cuda_runtime.h>
#include <cuda_bf16.h>
#include <cstdint>

#define L_HOPS 5
#define D_DIM  32
#define E_CAP  131072

#define BLOCK  256
#define BPSM   6
#define NSM    148
#define GRID   (NSM * BPSM)   // 888 blocks, all co-resident at <=40 regs

// AoS table: dots[e][l], 2.6 MB, L2-resident.
__device__ float g_table[(size_t)E_CAP * L_HOPS];

// Epoch ticket barrier counter (monotonic across graph replays).
__device__ unsigned long long g_bar = 0ULL;

// 1/max(len,1); len==0 -> 0 (sum is 0 anyway)
__constant__ float c_inv[8] = {0.0f, 1.0f, 0.5f, 1.0f / 3.0f, 0.25f, 0.2f, 0.0f, 0.0f};

__global__ void __launch_bounds__(BLOCK, BPSM) fused_edge_encoding(
    const float* __restrict__ edge_attr,   // [E, 32]
    const float* __restrict__ edge_vector, // [5, 32]
    const int*   __restrict__ path_edges,  // [P, 5]
    const int*   __restrict__ path_len,    // [P]
    float*       __restrict__ out,         // [P]
    int E, int P)
{
    const int tid = threadIdx.x;
    const int bid = blockIdx.x;

    __shared__ float sev[L_HOPS * D_DIM];     // 160 floats
    __shared__ float sdots[BLOCK * L_HOPS];   // 1280 floats (staging for coalesced store)

    if (tid < L_HOPS * D_DIM)
        sev[tid] = edge_vector[tid];
    __syncthreads();

    // ---- Phase A: dot table for edges [bid*256, bid*256+256) ------------
    {
        int e = bid * BLOCK + tid;            // 888*256 = 227328 >= E covers all
        float acc0 = 0.f, acc1 = 0.f, acc2 = 0.f, acc3 = 0.f, acc4 = 0.f;
        if (e < E) {
            const float4* row = reinterpret_cast<const float4*>(edge_attr + (size_t)e * D_DIM);
#pragma unroll
            for (int i = 0; i < D_DIM / 4; i++) {
                float4 v = row[i];
#pragma unroll
                for (int c = 0; c < 4; c++) {
                    float a = (c == 0) ? v.x : (c == 1) ? v.y : (c == 2) ? v.z : v.w;
                    int d = i * 4 + c;
                    acc0 = fmaf(a, sev[0 * D_DIM + d], acc0);
                    acc1 = fmaf(a, sev[1 * D_DIM + d], acc1);
                    acc2 = fmaf(a, sev[2 * D_DIM + d], acc2);
                    acc3 = fmaf(a, sev[3 * D_DIM + d], acc3);
                    acc4 = fmaf(a, sev[4 * D_DIM + d], acc4);
                }
            }
        }
        // stride-5 STS: (tid*5+l) % 32 distinct per fixed l -> conflict-free
        sdots[tid * 5 + 0] = acc0;
        sdots[tid * 5 + 1] = acc1;
        sdots[tid * 5 + 2] = acc2;
        sdots[tid * 5 + 3] = acc3;
        sdots[tid * 5 + 4] = acc4;
    }
    __syncthreads();

    // Coalesced float4 table writes: 320 float4 per block.
    {
        const float4* s4 = reinterpret_cast<const float4*>(sdots);
        float4* t4 = reinterpret_cast<float4*>(g_table);
        int table_f4 = (E * L_HOPS) / 4;      // 163840 for E=131072
#pragma unroll
        for (int k = 0; k < 2; k++) {
            int i = tid + k * BLOCK;          // 0..511, need < 320
            int gi = bid * (BLOCK * L_HOPS / 4) + i;
            if (i < BLOCK * L_HOPS / 4 && gi < table_f4)
                t4[gi] = s4[i];
        }
    }

    // ---- Device-wide epoch barrier (all GRID blocks resident) ------------
    __threadfence();
    __syncthreads();
    if (tid == 0) {
        unsigned long long ticket = atomicAdd(&g_bar, 1ULL);
        unsigned long long target = (ticket / GRID + 1ULL) * GRID;
        volatile unsigned long long* bar = &g_bar;
        while (*bar < target) { }
    }
    __syncthreads();
    __threadfence();

    // ---- Phase C: two quad slots per thread (R2 shape) -------------------
    const int Pq = P >> 2;
    const int4* __restrict__ gpe = reinterpret_cast<const int4*>(path_edges);
    const int4* __restrict__ gpl = reinterpret_cast<const int4*>(path_len);
    float4* __restrict__ go = reinterpret_cast<float4*>(out);

#pragma unroll
    for (int slot = 0; slot < 2; slot++) {
        int t = bid * BLOCK + tid + slot * (GRID * BLOCK);
        if (t < Pq) {
            const int4* pe = gpe + (size_t)t * 5;
            int4 a  = __ldg(pe + 0);
            int4 b  = __ldg(pe + 1);
            int4 c  = __ldg(pe + 2);
            int4 d  = __ldg(pe + 3);
            int4 e4 = __ldg(pe + 4);
            int4 ln = __ldg(gpl + t);

            float v00 = (ln.x > 0) ? __ldg(&g_table[(unsigned)a.x  * 5u + 0u]) : 0.f;
            float v01 = (ln.x > 1) ? __ldg(&g_table[(unsigned)a.y  * 5u + 1u]) : 0.f;
            float v02 = (ln.x > 2) ? __ldg(&g_table[(unsigned)a.z  * 5u + 2u]) : 0.f;
            float v03 = (ln.x > 3) ? __ldg(&g_table[(unsigned)a.w  * 5u + 3u]) : 0.f;
            float v04 = (ln.x > 4) ? __ldg(&g_table[(unsigned)b.x  * 5u + 4u]) : 0.f;

            float v10 = (ln.y > 0) ? __ldg(&g_table[(unsigned)b.y  * 5u + 0u]) : 0.f;
            float v11 = (ln.y > 1) ? __ldg(&g_table[(unsigned)b.z  * 5u + 1u]) : 0.f;
            float v12 = (ln.y > 2) ? __ldg(&g_table[(unsigned)b.w  * 5u + 2u]) : 0.f;
            float v13 = (ln.y > 3) ? __ldg(&g_table[(unsigned)c.x  * 5u + 3u]) : 0.f;
            float v14 = (ln.y > 4) ? __ldg(&g_table[(unsigned)c.y  * 5u + 4u]) : 0.f;

            float v20 = (ln.z > 0) ? __ldg(&g_table[(unsigned)c.z  * 5u + 0u]) : 0.f;
            float v21 = (ln.z > 1) ? __ldg(&g_table[(unsigned)c.w  * 5u + 1u]) : 0.f;
            float v22 = (ln.z > 2) ? __ldg(&g_table[(unsigned)d.x  * 5u + 2u]) : 0.f;
            float v23 = (ln.z > 3) ? __ldg(&g_table[(unsigned)d.y  * 5u + 3u]) : 0.f;
            float v24 = (ln.z > 4) ? __ldg(&g_table[(unsigned)d.z  * 5u + 4u]) : 0.f;

            float v30 = (ln.w > 0) ? __ldg(&g_table[(unsigned)d.w  * 5u + 0u]) : 0.f;
            float v31 = (ln.w > 1) ? __ldg(&g_table[(unsigned)e4.x * 5u + 1u]) : 0.f;
            float v32 = (ln.w > 2) ? __ldg(&g_table[(unsigned)e4.y * 5u + 2u]) : 0.f;
            float v33 = (ln.w > 3) ? __ldg(&g_table[(unsigned)e4.z * 5u + 3u]) : 0.f;
            float v34 = (ln.w > 4) ? __ldg(&g_table[(unsigned)e4.w * 5u + 4u]) : 0.f;

            float4 r;
            r.x = (((v00 + v01) + (v02 + v03)) + v04) * c_inv[ln.x & 7];
            r.y = (((v10 + v11) + (v12 + v13)) + v14) * c_inv[ln.y & 7];
            r.z = (((v20 + v21) + (v22 + v23)) + v24) * c_inv[ln.z & 7];
            r.w = (((v30 + v31) + (v32 + v33)) + v34) * c_inv[ln.w & 7];
            go[t] = r;
        }
    }

    // Scalar tail for P % 4 (not hit for N=1024).
    {
        int p = (Pq << 2) + bid * BLOCK + tid;
        if (p < P) {
            int len = __ldg(path_len + p);
            const int* row = path_edges + (size_t)p * L_HOPS;
            float s = 0.f;
#pragma unroll
            for (int l = 0; l < L_HOPS; l++)
                s += (len > l) ? __ldg(&g_table[(unsigned)row[l] * 5u + (unsigned)l]) : 0.f;
            out[p] = s * c_inv[len & 7];
        }
    }
}

// ---------------------------------------------------------------------------
// Inputs: x[N,32], edge_attr[E,32], edge_vector[5,32],
//         path_edges[P,5] (int32), path_len[P] (int32)  -> out float32 [P]
// ---------------------------------------------------------------------------
extern "C" void kernel_launch(void* const* d_in, const int* in_sizes, int n_in,
                              void* d_out, int out_size)
{
    const float* edge_attr   = (const float*)d_in[1];
    const float* edge_vector = (const float*)d_in[2];
    const int*   path_edges  = (const int*)d_in[3];
    const int*   path_len    = (const int*)d_in[4];
    float*       out         = (float*)d_out;

    int E = in_sizes[1] / D_DIM;
    int P = out_size;

    fused_edge_encoding<<<GRID, BLOCK>>>(
        edge_attr, edge_vector, path_edges, path_len, out, E, P);
}

// round 11
// speedup vs baseline: 1.1858x; 1.1858x over previous
#include <cuda_runtime.h>
#include <cuda_bf16.h>
#include <cstdint>

#define L_HOPS 5
#define D_DIM  32
#define E_CAP  131072

// AoS table: dots[e][l], 2.6 MB, L2-resident.
__device__ float g_table[(size_t)E_CAP * L_HOPS];

// 1/max(len,1); len==0 -> 0 (sum is 0 anyway)
__constant__ float c_inv[8] = {0.0f, 1.0f, 0.5f, 1.0f / 3.0f, 0.25f, 0.2f, 0.0f, 0.0f};

// ---------------------------------------------------------------------------
// Kernel 1: per-(edge, hop) dot products. One thread per edge (128 B row).
// Streaming reads (evict-first), L2-cached table writes.
// ---------------------------------------------------------------------------
__global__ void __launch_bounds__(256) precompute_dots_kernel(
    const float* __restrict__ edge_attr,   // [E, 32]
    const float* __restrict__ edge_vector, // [5, 32]
    int E)
{
    __shared__ float sev[L_HOPS * D_DIM];
    if (threadIdx.x < L_HOPS * D_DIM)
        sev[threadIdx.x] = edge_vector[threadIdx.x];
    __syncthreads();

    int e = blockIdx.x * blockDim.x + threadIdx.x;
    if (e >= E) return;

    const float4* row = reinterpret_cast<const float4*>(edge_attr + (size_t)e * D_DIM);

    float acc0 = 0.f, acc1 = 0.f, acc2 = 0.f, acc3 = 0.f, acc4 = 0.f;
#pragma unroll
    for (int i = 0; i < D_DIM / 4; i++) {
        float4 v = __ldcs(row + i);   // streaming: don't pollute L2
#pragma unroll
        for (int c = 0; c < 4; c++) {
            float a = (c == 0) ? v.x : (c == 1) ? v.y : (c == 2) ? v.z : v.w;
            int d = i * 4 + c;
            acc0 = fmaf(a, sev[0 * D_DIM + d], acc0);
            acc1 = fmaf(a, sev[1 * D_DIM + d], acc1);
            acc2 = fmaf(a, sev[2 * D_DIM + d], acc2);
            acc3 = fmaf(a, sev[3 * D_DIM + d], acc3);
            acc4 = fmaf(a, sev[4 * D_DIM + d], acc4);
        }
    }

    float* t = g_table + (size_t)e * L_HOPS;
    __stcg(t + 0, acc0);   // cache in L2 (the gather kernel wants these resident)
    __stcg(t + 1, acc1);
    __stcg(t + 2, acc2);
    __stcg(t + 3, acc3);
    __stcg(t + 4, acc4);
}

// ---------------------------------------------------------------------------
// Kernel 2: R2 structure (4 pairs/thread, block 256 — best measured shape),
// with cache-operator changes:
//   - gathers:  __ldcg  (L2-only, no L1 fill allocation)
//   - streams:  __ldcs  (evict-first in L2)
//   - output:   __stcs  (evict-first in L2)
// ---------------------------------------------------------------------------
__global__ void __launch_bounds__(256) pair_reduce_kernel4(
    const int* __restrict__ path_edges,  // [P, 5]
    const int* __restrict__ path_len,    // [P]
    float* __restrict__ out,             // [P]
    int Pq)                              // P / 4
{
    int t = blockIdx.x * blockDim.x + threadIdx.x;
    if (t >= Pq) return;

    // 4 pairs: 20 indices = 5 x int4 (80 B, 16B-aligned), lens = 1 x int4.
    const int4* pe = reinterpret_cast<const int4*>(path_edges) + (size_t)t * 5;
    int4 a  = __ldcs(pe + 0);
    int4 b  = __ldcs(pe + 1);
    int4 c  = __ldcs(pe + 2);
    int4 d  = __ldcs(pe + 3);
    int4 e4 = __ldcs(pe + 4);
    int4 ln = __ldcs(reinterpret_cast<const int4*>(path_len) + t);

    // Predicated L2-direct gathers (no L1 allocation).
    float v00 = (ln.x > 0) ? __ldcg(&g_table[(unsigned)a.x  * 5u + 0u]) : 0.f;
    float v01 = (ln.x > 1) ? __ldcg(&g_table[(unsigned)a.y  * 5u + 1u]) : 0.f;
    float v02 = (ln.x > 2) ? __ldcg(&g_table[(unsigned)a.z  * 5u + 2u]) : 0.f;
    float v03 = (ln.x > 3) ? __ldcg(&g_table[(unsigned)a.w  * 5u + 3u]) : 0.f;
    float v04 = (ln.x > 4) ? __ldcg(&g_table[(unsigned)b.x  * 5u + 4u]) : 0.f;

    float v10 = (ln.y > 0) ? __ldcg(&g_table[(unsigned)b.y  * 5u + 0u]) : 0.f;
    float v11 = (ln.y > 1) ? __ldcg(&g_table[(unsigned)b.z  * 5u + 1u]) : 0.f;
    float v12 = (ln.y > 2) ? __ldcg(&g_table[(unsigned)b.w  * 5u + 2u]) : 0.f;
    float v13 = (ln.y > 3) ? __ldcg(&g_table[(unsigned)c.x  * 5u + 3u]) : 0.f;
    float v14 = (ln.y > 4) ? __ldcg(&g_table[(unsigned)c.y  * 5u + 4u]) : 0.f;

    float v20 = (ln.z > 0) ? __ldcg(&g_table[(unsigned)c.z  * 5u + 0u]) : 0.f;
    float v21 = (ln.z > 1) ? __ldcg(&g_table[(unsigned)c.w  * 5u + 1u]) : 0.f;
    float v22 = (ln.z > 2) ? __ldcg(&g_table[(unsigned)d.x  * 5u + 2u]) : 0.f;
    float v23 = (ln.z > 3) ? __ldcg(&g_table[(unsigned)d.y  * 5u + 3u]) : 0.f;
    float v24 = (ln.z > 4) ? __ldcg(&g_table[(unsigned)d.z  * 5u + 4u]) : 0.f;

    float v30 = (ln.w > 0) ? __ldcg(&g_table[(unsigned)d.w  * 5u + 0u]) : 0.f;
    float v31 = (ln.w > 1) ? __ldcg(&g_table[(unsigned)e4.x * 5u + 1u]) : 0.f;
    float v32 = (ln.w > 2) ? __ldcg(&g_table[(unsigned)e4.y * 5u + 2u]) : 0.f;
    float v33 = (ln.w > 3) ? __ldcg(&g_table[(unsigned)e4.z * 5u + 3u]) : 0.f;
    float v34 = (ln.w > 4) ? __ldcg(&g_table[(unsigned)e4.w * 5u + 4u]) : 0.f;

    float4 r;
    r.x = (((v00 + v01) + (v02 + v03)) + v04) * c_inv[ln.x & 7];
    r.y = (((v10 + v11) + (v12 + v13)) + v14) * c_inv[ln.y & 7];
    r.z = (((v20 + v21) + (v22 + v23)) + v24) * c_inv[ln.z & 7];
    r.w = (((v30 + v31) + (v32 + v33)) + v34) * c_inv[ln.w & 7];
    __stcs(reinterpret_cast<float4*>(out) + t, r);
}

// Scalar fallback for P not divisible by 4 (not hit for N=1024).
__global__ void pair_reduce_tail(
    const int* __restrict__ path_edges,
    const int* __restrict__ path_len,
    float* __restrict__ out,
    int start, int P)
{
    int p = start + blockIdx.x * blockDim.x + threadIdx.x;
    if (p >= P) return;
    int len = path_len[p];
    const int* row = path_edges + (size_t)p * L_HOPS;
    float s = 0.f;
#pragma unroll
    for (int l = 0; l < L_HOPS; l++)
        s += (len > l) ? __ldcg(&g_table[(unsigned)row[l] * 5u + (unsigned)l]) : 0.f;
    out[p] = s * c_inv[len & 7];
}

// ---------------------------------------------------------------------------
// Inputs: x[N,32], edge_attr[E,32], edge_vector[5,32],
//         path_edges[P,5] (int32), path_len[P] (int32)  -> out float32 [P]
// ---------------------------------------------------------------------------
extern "C" void kernel_launch(void* const* d_in, const int* in_sizes, int n_in,
                              void* d_out, int out_size)
{
    const float* edge_attr   = (const float*)d_in[1];
    const float* edge_vector = (const float*)d_in[2];
    const int*   path_edges  = (const int*)d_in[3];
    const int*   path_len    = (const int*)d_in[4];
    float*       out         = (float*)d_out;

    int E = in_sizes[1] / D_DIM;
    int P = out_size;

    {
        int threads = 256;
        int blocks = (E + threads - 1) / threads;
        precompute_dots_kernel<<<blocks, threads>>>(edge_attr, edge_vector, E);
    }
    int Pq = P / 4;
    if (Pq > 0) {
        int threads = 256;
        int blocks = (Pq + threads - 1) / threads;
        pair_reduce_kernel4<<<blocks, threads>>>(path_edges, path_len, out, Pq);
    }
    int done = Pq * 4;
    if (done < P) {
        int rem = P - done;
        pair_reduce_tail<<<(rem + 255) / 256, 256>>>(path_edges, path_len, out, done, P);
    }
}

// round 12
// speedup vs baseline: 1.1980x; 1.0102x over previous
#include <cuda_runtime.h>
#include <cuda_bf16.h>
#include <cstdint>

#define L_HOPS 5
#define D_DIM  32
#define E_CAP  131072
#define PRE_BLOCK 256

// AoS table: dots[e][l], 2.6 MB, L2-resident (best gather layout).
__device__ float g_table[(size_t)E_CAP * L_HOPS];

// 1/max(len,1); len==0 -> 0 (sum is 0 anyway)
__constant__ float c_inv[8] = {0.0f, 1.0f, 0.5f, 1.0f / 3.0f, 0.25f, 0.2f, 0.0f, 0.0f};

// ---------------------------------------------------------------------------
// Kernel 1: per-(edge, hop) dot products, one thread per edge.
// Table writes staged through smem: stride-5 STS (conflict-free since
// gcd(5,32)=1) then fully-coalesced float4 STG — 20 store wavefronts per warp
// instead of 100.
// ---------------------------------------------------------------------------
__global__ void __launch_bounds__(PRE_BLOCK) precompute_dots_kernel(
    const float* __restrict__ edge_attr,   // [E, 32]
    const float* __restrict__ edge_vector, // [5, 32]
    int E)
{
    __shared__ float sev[L_HOPS * D_DIM];           // 160 floats
    __shared__ float sdots[PRE_BLOCK * L_HOPS];     // 1280 floats

    const int tid = threadIdx.x;
    if (tid < L_HOPS * D_DIM)
        sev[tid] = edge_vector[tid];
    __syncthreads();

    int e = blockIdx.x * PRE_BLOCK + tid;

    float acc0 = 0.f, acc1 = 0.f, acc2 = 0.f, acc3 = 0.f, acc4 = 0.f;
    if (e < E) {
        const float4* row = reinterpret_cast<const float4*>(edge_attr + (size_t)e * D_DIM);
#pragma unroll
        for (int i = 0; i < D_DIM / 4; i++) {
            float4 v = __ldg(row + i);
#pragma unroll
            for (int c = 0; c < 4; c++) {
                float a = (c == 0) ? v.x : (c == 1) ? v.y : (c == 2) ? v.z : v.w;
                int d = i * 4 + c;
                acc0 = fmaf(a, sev[0 * D_DIM + d], acc0);
                acc1 = fmaf(a, sev[1 * D_DIM + d], acc1);
                acc2 = fmaf(a, sev[2 * D_DIM + d], acc2);
                acc3 = fmaf(a, sev[3 * D_DIM + d], acc3);
                acc4 = fmaf(a, sev[4 * D_DIM + d], acc4);
            }
        }
    }

    // stride-5 STS: banks (tid*5+l) mod 32 all distinct per fixed l.
    sdots[tid * 5 + 0] = acc0;
    sdots[tid * 5 + 1] = acc1;
    sdots[tid * 5 + 2] = acc2;
    sdots[tid * 5 + 3] = acc3;
    sdots[tid * 5 + 4] = acc4;
    __syncthreads();

    // Coalesced float4 table writes: 320 float4 per block (bounds-safe since
    // grid covers E exactly when E % 256 == 0; guarded otherwise).
    const float4* s4 = reinterpret_cast<const float4*>(sdots);
    float4* t4 = reinterpret_cast<float4*>(g_table);
    int table_f4 = (E * L_HOPS) / 4;
    int base_f4  = blockIdx.x * (PRE_BLOCK * L_HOPS / 4);
#pragma unroll
    for (int k = 0; k < 2; k++) {
        int i = tid + k * PRE_BLOCK;                 // 0..511, need < 320
        if (i < PRE_BLOCK * L_HOPS / 4) {
            int gi = base_f4 + i;
            if (gi < table_f4)
                t4[gi] = s4[i];
        }
    }
}

// ---------------------------------------------------------------------------
// Kernel 2: exact R2 shape (best measured: 17.0 us).
// 4 pairs/thread, vectorized streams, predicated __ldg gathers.
// ---------------------------------------------------------------------------
__global__ void __launch_bounds__(256) pair_reduce_kernel4(
    const int* __restrict__ path_edges,  // [P, 5]
    const int* __restrict__ path_len,    // [P]
    float* __restrict__ out,             // [P]
    int Pq)                              // P / 4
{
    int t = blockIdx.x * blockDim.x + threadIdx.x;
    if (t >= Pq) return;

    const int4* pe = reinterpret_cast<const int4*>(path_edges) + (size_t)t * 5;
    int4 a  = __ldg(pe + 0);
    int4 b  = __ldg(pe + 1);
    int4 c  = __ldg(pe + 2);
    int4 d  = __ldg(pe + 3);
    int4 e4 = __ldg(pe + 4);
    int4 ln = __ldg(reinterpret_cast<const int4*>(path_len) + t);

    float v00 = (ln.x > 0) ? __ldg(&g_table[(unsigned)a.x  * 5u + 0u]) : 0.f;
    float v01 = (ln.x > 1) ? __ldg(&g_table[(unsigned)a.y  * 5u + 1u]) : 0.f;
    float v02 = (ln.x > 2) ? __ldg(&g_table[(unsigned)a.z  * 5u + 2u]) : 0.f;
    float v03 = (ln.x > 3) ? __ldg(&g_table[(unsigned)a.w  * 5u + 3u]) : 0.f;
    float v04 = (ln.x > 4) ? __ldg(&g_table[(unsigned)b.x  * 5u + 4u]) : 0.f;

    float v10 = (ln.y > 0) ? __ldg(&g_table[(unsigned)b.y  * 5u + 0u]) : 0.f;
    float v11 = (ln.y > 1) ? __ldg(&g_table[(unsigned)b.z  * 5u + 1u]) : 0.f;
    float v12 = (ln.y > 2) ? __ldg(&g_table[(unsigned)b.w  * 5u + 2u]) : 0.f;
    float v13 = (ln.y > 3) ? __ldg(&g_table[(unsigned)c.x  * 5u + 3u]) : 0.f;
    float v14 = (ln.y > 4) ? __ldg(&g_table[(unsigned)c.y  * 5u + 4u]) : 0.f;

    float v20 = (ln.z > 0) ? __ldg(&g_table[(unsigned)c.z  * 5u + 0u]) : 0.f;
    float v21 = (ln.z > 1) ? __ldg(&g_table[(unsigned)c.w  * 5u + 1u]) : 0.f;
    float v22 = (ln.z > 2) ? __ldg(&g_table[(unsigned)d.x  * 5u + 2u]) : 0.f;
    float v23 = (ln.z > 3) ? __ldg(&g_table[(unsigned)d.y  * 5u + 3u]) : 0.f;
    float v24 = (ln.z > 4) ? __ldg(&g_table[(unsigned)d.z  * 5u + 4u]) : 0.f;

    float v30 = (ln.w > 0) ? __ldg(&g_table[(unsigned)d.w  * 5u + 0u]) : 0.f;
    float v31 = (ln.w > 1) ? __ldg(&g_table[(unsigned)e4.x * 5u + 1u]) : 0.f;
    float v32 = (ln.w > 2) ? __ldg(&g_table[(unsigned)e4.y * 5u + 2u]) : 0.f;
    float v33 = (ln.w > 3) ? __ldg(&g_table[(unsigned)e4.z * 5u + 3u]) : 0.f;
    float v34 = (ln.w > 4) ? __ldg(&g_table[(unsigned)e4.w * 5u + 4u]) : 0.f;

    float4 r;
    r.x = (((v00 + v01) + (v02 + v03)) + v04) * c_inv[ln.x & 7];
    r.y = (((v10 + v11) + (v12 + v13)) + v14) * c_inv[ln.y & 7];
    r.z = (((v20 + v21) + (v22 + v23)) + v24) * c_inv[ln.z & 7];
    r.w = (((v30 + v31) + (v32 + v33)) + v34) * c_inv[ln.w & 7];
    reinterpret_cast<float4*>(out)[t] = r;
}

// Scalar fallback for P not divisible by 4 (not hit for N=1024).
__global__ void pair_reduce_tail(
    const int* __restrict__ path_edges,
    const int* __restrict__ path_len,
    float* __restrict__ out,
    int start, int P)
{
    int p = start + blockIdx.x * blockDim.x + threadIdx.x;
    if (p >= P) return;
    int len = path_len[p];
    const int* row = path_edges + (size_t)p * L_HOPS;
    float s = 0.f;
#pragma unroll
    for (int l = 0; l < L_HOPS; l++)
        s += (len > l) ? __ldg(&g_table[(unsigned)row[l] * 5u + (unsigned)l]) : 0.f;
    out[p] = s * c_inv[len & 7];
}

// ---------------------------------------------------------------------------
// Inputs: x[N,32], edge_attr[E,32], edge_vector[5,32],
//         path_edges[P,5] (int32), path_len[P] (int32)  -> out float32 [P]
// ---------------------------------------------------------------------------
extern "C" void kernel_launch(void* const* d_in, const int* in_sizes, int n_in,
                              void* d_out, int out_size)
{
    const float* edge_attr   = (const float*)d_in[1];
    const float* edge_vector = (const float*)d_in[2];
    const int*   path_edges  = (const int*)d_in[3];
    const int*   path_len    = (const int*)d_in[4];
    float*       out         = (float*)d_out;

    int E = in_sizes[1] / D_DIM;
    int P = out_size;

    {
        int blocks = (E + PRE_BLOCK - 1) / PRE_BLOCK;
        precompute_dots_kernel<<<blocks, PRE_BLOCK>>>(edge_attr, edge_vector, E);
    }
    int Pq = P / 4;
    if (Pq > 0) {
        int threads = 256;
        int blocks = (Pq + threads - 1) / threads;
        pair_reduce_kernel4<<<blocks, threads>>>(path_edges, path_len, out, Pq);
    }
    int done = Pq * 4;
    if (done < P) {
        int rem = P - done;
        pair_reduce_tail<<<(rem + 255) / 256, 256>>>(path_edges, path_len, out, done, P);
    }
}